// round 14
// baseline (speedup 1.0000x reference)
#include <cuda_runtime.h>
#include <cstdint>

#define Bq   8
#define Nn   5000
#define Ee   40000
#define Ff   64
#define FEe  16
#define FIL  96
#define DM   144
#define DU   160
#define LN_EPS 1e-3f
#define MSTR 104   // node Ms row stride (words)
#define EMSTR 100  // edge Ms row stride (words) — bank-clean for quad LDS + STS
#define NT   (Bq * Nn)

__device__ __align__(16) float g_agg[(size_t)Bq * Nn * FIL];
__device__ __align__(16) float g_pre[(size_t)Bq * Nn * 192];   // [node][0:96]=src-term, [96:192]=dst-term

// packed bf16 hi/lo weight fragments (built once by pack_kernel)
__device__ __align__(16) uint4 g_Wpre[16 * 192];   // pre B: combined [Wm(0:64)|Wm(64:128)]
__device__ __align__(16) uint4 g_Wef[4 * 96];      // edge B: Wm[128:144]
__device__ __align__(16) uint4 g_Wun[40 * 96];     // node B: Wu

// ---------------- helpers ----------------
__device__ __forceinline__ void red4(float* addr, float4 v) {
    asm volatile("red.global.add.v4.f32 [%0], {%1,%2,%3,%4};"
                 :: "l"(addr), "f"(v.x), "f"(v.y), "f"(v.z), "f"(v.w) : "memory");
}
__device__ __forceinline__ uint32_t split_pair(float x, float y, uint32_t& lo2) {
    uint32_t h;
    asm("cvt.rn.bf16x2.f32 %0, %1, %2;" : "=r"(h) : "f"(y), "f"(x));
    float hx = __uint_as_float(h << 16);
    float hy = __uint_as_float(h & 0xffff0000u);
    float rx = x - hx, ry = y - hy;
    asm("cvt.rn.bf16x2.f32 %0, %1, %2;" : "=r"(lo2) : "f"(ry), "f"(rx));
    return h;
}
__device__ __forceinline__ void mma_bf16(float* c, const uint32_t* a,
                                         uint32_t b0, uint32_t b1) {
    asm volatile(
        "mma.sync.aligned.m16n8k16.row.col.f32.bf16.bf16.f32 "
        "{%0,%1,%2,%3}, {%4,%5,%6,%7}, {%8,%9}, {%0,%1,%2,%3};"
        : "+f"(c[0]), "+f"(c[1]), "+f"(c[2]), "+f"(c[3])
        : "r"(a[0]), "r"(a[1]), "r"(a[2]), "r"(a[3]), "r"(b0), "r"(b1));
}
__device__ __forceinline__ void load_split(const float* p, int off,
                                           uint32_t& h0, uint32_t& h2,
                                           uint32_t& l0, uint32_t& l2) {
    float2 x0 = *(const float2*)(p + off);
    float2 x2 = *(const float2*)(p + off + 8);
    h0 = split_pair(x0.x, x0.y, l0);
    h2 = split_pair(x2.x, x2.y, l2);
}

// ================= pack kernel (unchanged) =================
__global__ void __launch_bounds__(256) pack_kernel(
    const float* __restrict__ Wm, const float* __restrict__ Wu)
{
    const int t = threadIdx.x;
    const size_t gtid = (size_t)blockIdx.x * 256 + t;
    const size_t gstr = (size_t)gridDim.x * 256;

    {
        float4* p = (float4*)g_agg;
        for (size_t i = gtid; i < (size_t)NT * FIL / 4; i += gstr)
            p[i] = make_float4(0.f, 0.f, 0.f, 0.f);
    }
    for (size_t i = gtid; i < 16 * 192; i += gstr) {
        int slot = (int)i / 192, n = (int)i - slot * 192;
        int kt = slot >> 2, qs = slot & 3;
        int ka = (kt * 8 + qs) * 2;
        int kb = ka + 8;
        const int col = (n < 96) ? n : (n - 96);
        const int ro  = (n < 96) ? 0 : 64;
        uint32_t la, lb;
        uint32_t ha = split_pair(Wm[(ro + ka) * FIL + col], Wm[(ro + ka + 1) * FIL + col], la);
        uint32_t hb = split_pair(Wm[(ro + kb) * FIL + col], Wm[(ro + kb + 1) * FIL + col], lb);
        g_Wpre[slot * 192 + (n ^ (2 * qs))] = make_uint4(ha, hb, la, lb);
    }
    for (size_t i = gtid; i < 4 * 96; i += gstr) {
        int qs = (int)i / 96, n = (int)i - qs * 96;
        uint32_t la, lb;
        uint32_t ha = split_pair(Wm[(128 + 2 * qs) * FIL + n], Wm[(129 + 2 * qs) * FIL + n], la);
        uint32_t hb = split_pair(Wm[(136 + 2 * qs) * FIL + n], Wm[(137 + 2 * qs) * FIL + n], lb);
        g_Wef[qs * 96 + (n ^ (2 * qs))] = make_uint4(ha, hb, la, lb);
    }
    for (size_t i = gtid; i < 40 * 96; i += gstr) {
        int slot = (int)i / 96, n = (int)i - slot * 96;
        int kt = slot >> 2, q = slot & 3;
        int k2a = kt * 8 + q, k2b = k2a + 4;
        uint32_t la, lb;
        uint32_t ha = split_pair(Wu[(2 * k2a) * FIL + n], Wu[(2 * k2a + 1) * FIL + n], la);
        uint32_t hb = split_pair(Wu[(2 * k2b) * FIL + n], Wu[(2 * k2b + 1) * FIL + n], lb);
        g_Wun[slot * 96 + (n ^ (2 * q))] = make_uint4(ha, hb, la, lb);
    }
}

// ================= pre kernel: 64 rows/block, warp-pair N-split =================
__global__ void __launch_bounds__(256, 3) pre_kernel(
    const float* __restrict__ nodes)
{
    const int t = threadIdx.x;
    const int lane = t & 31;
    const int w    = t >> 5;          // 0..7
    const int wg   = w >> 1;          // row group 0..3
    const int half = w & 1;           // N half
    const int g    = lane >> 2;
    const int q    = lane & 3;
    const int r0 = wg * 16 + g;
    const int gn0 = blockIdx.x * 64 + r0;
    const int gn1 = gn0 + 8;
    const int g0c = gn0 < NT ? gn0 : NT - 1;
    const int g1c = gn1 < NT ? gn1 : NT - 1;
    const float* n0 = nodes + (size_t)g0c * Ff;
    const float* n1 = nodes + (size_t)g1c * Ff;

    float c[12][4];
    #pragma unroll
    for (int nt = 0; nt < 12; nt++) { c[nt][0]=0.f; c[nt][1]=0.f; c[nt][2]=0.f; c[nt][3]=0.f; }

    const int gsw = g ^ (2 * q);
    const int qo  = 2 * q;
    const int ntb = half * 12;

    #pragma unroll
    for (int kt = 0; kt < 4; kt++) {
        uint32_t ah[4], al[4];
        load_split(n0, kt * 16 + qo, ah[0], ah[2], al[0], al[2]);
        load_split(n1, kt * 16 + qo, ah[1], ah[3], al[1], al[3]);
        const uint4* Bp = g_Wpre + (kt * 4 + q) * 192 + gsw + ntb * 8;
        #pragma unroll
        for (int nt = 0; nt < 12; nt++) {
            uint4 Bv = Bp[nt * 8];
            mma_bf16(c[nt], ah, Bv.x, Bv.y);
            mma_bf16(c[nt], al, Bv.x, Bv.y);
            mma_bf16(c[nt], ah, Bv.z, Bv.w);
        }
    }

    if (gn0 < NT) {
        float* o = g_pre + (size_t)gn0 * 192 + ntb * 8 + qo;
        #pragma unroll
        for (int nt = 0; nt < 12; nt++)
            *(float2*)(o + nt * 8) = make_float2(c[nt][0], c[nt][1]);
    }
    if (gn1 < NT) {
        float* o = g_pre + (size_t)gn1 * 192 + ntb * 8 + qo;
        #pragma unroll
        for (int nt = 0; nt < 12; nt++)
            *(float2*)(o + nt * 8) = make_float2(c[nt][2], c[nt][3]);
    }
}

// ================= edge kernel: coalesced smem-staged gather =================
#define XS_MS    0                       // 128 x 100 = 12800 words
#define XS_BM    12800
#define XS_GM    12896
#define XS_BT    12992
#define XS_SEB   13088                   // 128 int2 = 256 words
#define XS_TOTAL 13344
#define E_SMEM_BYTES (XS_TOTAL * 4)

__global__ void __launch_bounds__(256, 3) edge_kernel_mma(
    const float* __restrict__ ef,    const int*   __restrict__ edges,
    const float* __restrict__ bm,    const float* __restrict__ gm,
    const float* __restrict__ bt,    float* __restrict__ msg_out)
{
    extern __shared__ float sm[];
    float* Ms   = sm + XS_MS;         // stride EMSTR
    float* bm_s = sm + XS_BM;
    float* gm_s = sm + XS_GM;
    float* bt_s = sm + XS_BT;
    int2*  seb  = (int2*)(sm + XS_SEB);

    const int t = threadIdx.x;

    if (t < FIL) { bm_s[t] = bm[t]; gm_s[t] = gm[t]; bt_s[t] = bt[t]; }
    if (t < 128) seb[t] = ((const int2*)edges)[blockIdx.x * 128 + t];
    __syncthreads();

    // ---- phase 1: coalesced gather of g_pre src+dst sums into Ms ----
    #pragma unroll
    for (int it = 0; it < 12; it++) {
        const int i   = t + it * 256;          // 0..3071
        const int row = i / 24;
        const int c4  = i - row * 24;
        const int ge  = blockIdx.x * 128 + row;
        const int b   = ge / Ee;
        const int2 se = seb[row];
        const float4 s4 = *(const float4*)(g_pre + (size_t)(b * Nn + se.x) * 192 + c4 * 4);
        const float4 d4 = *(const float4*)(g_pre + (size_t)(b * Nn + se.y) * 192 + 96 + c4 * 4);
        *(float4*)(Ms + row * EMSTR + c4 * 4) =
            make_float4(s4.x + d4.x, s4.y + d4.y, s4.z + d4.z, s4.w + d4.w);
    }
    __syncthreads();

    const int lane = t & 31;
    const int w    = t >> 5;
    const int g    = lane >> 2;
    const int q    = lane & 3;
    const int r0 = w * 16 + g, r1 = r0 + 8;
    const int ge0 = blockIdx.x * 128 + r0;
    const int ge1 = ge0 + 8;
    const int gsw = g ^ (2 * q);
    const int qo  = 2 * q;

    // ---- phase 2: init accumulators from Ms + bias ----
    float c[12][4];
    #pragma unroll
    for (int nt = 0; nt < 12; nt++) {
        const int j = nt * 8 + qo;
        float2 v0 = *(const float2*)(Ms + r0 * EMSTR + j);
        float2 v1 = *(const float2*)(Ms + r1 * EMSTR + j);
        const float bv0 = bm_s[j], bv1 = bm_s[j + 1];
        c[nt][0] = v0.x + bv0;
        c[nt][1] = v0.y + bv1;
        c[nt][2] = v1.x + bv0;
        c[nt][3] = v1.y + bv1;
    }

    // ---- ef GEMM accumulates on top: single k-step, 3 terms ----
    {
        uint32_t ah[4], al[4];
        load_split(ef + (size_t)ge0 * FEe, qo, ah[0], ah[2], al[0], al[2]);
        load_split(ef + (size_t)ge1 * FEe, qo, ah[1], ah[3], al[1], al[3]);
        const uint4* Bp = g_Wef + q * 96 + gsw;
        #pragma unroll
        for (int nt = 0; nt < 12; nt++) {
            uint4 Bv = Bp[nt * 8];
            mma_bf16(c[nt], ah, Bv.x, Bv.y);
            mma_bf16(c[nt], al, Bv.x, Bv.y);
            mma_bf16(c[nt], ah, Bv.z, Bv.w);
        }
    }

    // ---- relu + LN stats ----
    float sum0 = 0.f, sq0 = 0.f, sum1 = 0.f, sq1 = 0.f;
    #pragma unroll
    for (int nt = 0; nt < 12; nt++) {
        float v0 = fmaxf(c[nt][0], 0.f);
        float v1 = fmaxf(c[nt][1], 0.f);
        float v2 = fmaxf(c[nt][2], 0.f);
        float v3 = fmaxf(c[nt][3], 0.f);
        c[nt][0] = v0; c[nt][1] = v1; c[nt][2] = v2; c[nt][3] = v3;
        sum0 += v0 + v1;  sq0 += v0 * v0 + v1 * v1;
        sum1 += v2 + v3;  sq1 += v2 * v2 + v3 * v3;
    }
    #pragma unroll
    for (int m = 1; m < 4; m <<= 1) {
        sum0 += __shfl_xor_sync(0xffffffffu, sum0, m);
        sq0  += __shfl_xor_sync(0xffffffffu, sq0,  m);
        sum1 += __shfl_xor_sync(0xffffffffu, sum1, m);
        sq1  += __shfl_xor_sync(0xffffffffu, sq1,  m);
    }
    const float mean0 = sum0 * (1.f / FIL);
    const float rstd0 = rsqrtf(sq0 * (1.f / FIL) - mean0 * mean0 + LN_EPS);
    const float mean1 = sum1 * (1.f / FIL);
    const float rstd1 = rsqrtf(sq1 * (1.f / FIL) - mean1 * mean1 + LN_EPS);

    // ---- apply LN, stage back to Ms (same ownership, no hazard) ----
    #pragma unroll
    for (int nt = 0; nt < 12; nt++) {
        const int j = nt * 8 + qo;
        const float g0 = gm_s[j], g1 = gm_s[j + 1];
        const float t0 = bt_s[j], t1 = bt_s[j + 1];
        *(float2*)(Ms + r0 * EMSTR + j) = make_float2(
            (c[nt][0] - mean0) * rstd0 * g0 + t0,
            (c[nt][1] - mean0) * rstd0 * g1 + t1);
        *(float2*)(Ms + r1 * EMSTR + j) = make_float2(
            (c[nt][2] - mean1) * rstd1 * g0 + t0,
            (c[nt][3] - mean1) * rstd1 * g1 + t1);
    }
    __syncthreads();

    // ---- coalesced store + vector atomics ----
    #pragma unroll
    for (int it = 0; it < 12; it++) {
        const int i   = t + it * 256;
        const int row = i / 24;
        const int c4  = i - row * 24;
        const int j   = c4 * 4;
        float4 o = *(const float4*)(Ms + row * EMSTR + j);
        const int ge = blockIdx.x * 128 + row;
        const int b  = ge / Ee;
        ((float4*)(msg_out + (size_t)ge * FIL))[c4] = o;
        red4(g_agg + ((size_t)b * Nn + seb[row].y) * FIL + j, o);
    }
}

// ================= node kernel (unchanged from R13) =================
#define NS_MS    0             // 128 x 104 = 13312 words
#define NS_BM    13312
#define NS_GM    13408
#define NS_BT    13504
#define NS_TOTAL 13600
#define N_SMEM_BYTES (NS_TOTAL * 4)

__global__ void __launch_bounds__(256, 2) node_kernel_mma(
    const float* __restrict__ nodes, const float* __restrict__ bu,
    const float* __restrict__ gm,    const float* __restrict__ bt,
    float* __restrict__ upd_out)
{
    extern __shared__ float sm[];
    float* Ms   = sm + NS_MS;
    float* bm_s = sm + NS_BM;
    float* gm_s = sm + NS_GM;
    float* bt_s = sm + NS_BT;

    const int t = threadIdx.x;

    if (t < FIL) { bm_s[t] = bu[t]; gm_s[t] = gm[t]; bt_s[t] = bt[t]; }
    __syncthreads();

    const int lane = t & 31;
    const int w    = t >> 5;
    const int g    = lane >> 2;
    const int q    = lane & 3;
    const int r0 = w * 16 + g, r1 = r0 + 8;

    const int gn0 = blockIdx.x * 128 + r0;
    const int gn1 = gn0 + 8;
    const int g0c = gn0 < NT ? gn0 : NT - 1;
    const int g1c = gn1 < NT ? gn1 : NT - 1;
    const float* n0 = nodes + (size_t)g0c * Ff;
    const float* n1 = nodes + (size_t)g1c * Ff;
    const float* a0 = g_agg + (size_t)g0c * FIL;
    const float* a1 = g_agg + (size_t)g1c * FIL;

    float c[12][4];
    #pragma unroll
    for (int nt = 0; nt < 12; nt++) { c[nt][0]=0.f; c[nt][1]=0.f; c[nt][2]=0.f; c[nt][3]=0.f; }

    const int gsw = g ^ (2 * q);
    const int qo  = 2 * q;

    #pragma unroll
    for (int kt = 0; kt < 10; kt++) {
        const float *p0, *p1;
        int off;
        if (kt < 4) { p0 = n0; p1 = n1; off = kt * 16; }
        else        { p0 = a0; p1 = a1; off = (kt - 4) * 16; }
        off += qo;

        uint32_t ah[4], al[4];
        load_split(p0, off, ah[0], ah[2], al[0], al[2]);
        load_split(p1, off, ah[1], ah[3], al[1], al[3]);

        const uint4* Bp = g_Wun + (kt * 4 + q) * 96 + gsw;
        #pragma unroll
        for (int nt = 0; nt < 12; nt++) {
            uint4 Bv = Bp[nt * 8];
            mma_bf16(c[nt], ah, Bv.x, Bv.y);
            mma_bf16(c[nt], al, Bv.x, Bv.y);
            mma_bf16(c[nt], ah, Bv.z, Bv.w);
        }
    }

    float sum0 = 0.f, sq0 = 0.f, sum1 = 0.f, sq1 = 0.f;
    #pragma unroll
    for (int nt = 0; nt < 12; nt++) {
        const int j = nt * 8 + qo;
        const float bv0 = bm_s[j], bv1 = bm_s[j + 1];
        float v0 = fmaxf(c[nt][0] + bv0, 0.f);
        float v1 = fmaxf(c[nt][1] + bv1, 0.f);
        float v2 = fmaxf(c[nt][2] + bv0, 0.f);
        float v3 = fmaxf(c[nt][3] + bv1, 0.f);
        c[nt][0] = v0; c[nt][1] = v1; c[nt][2] = v2; c[nt][3] = v3;
        sum0 += v0 + v1;  sq0 += v0 * v0 + v1 * v1;
        sum1 += v2 + v3;  sq1 += v2 * v2 + v3 * v3;
    }
    #pragma unroll
    for (int m = 1; m < 4; m <<= 1) {
        sum0 += __shfl_xor_sync(0xffffffffu, sum0, m);
        sq0  += __shfl_xor_sync(0xffffffffu, sq0,  m);
        sum1 += __shfl_xor_sync(0xffffffffu, sum1, m);
        sq1  += __shfl_xor_sync(0xffffffffu, sq1,  m);
    }
    const float mean0 = sum0 * (1.f / FIL);
    const float rstd0 = rsqrtf(sq0 * (1.f / FIL) - mean0 * mean0 + LN_EPS);
    const float mean1 = sum1 * (1.f / FIL);
    const float rstd1 = rsqrtf(sq1 * (1.f / FIL) - mean1 * mean1 + LN_EPS);

    #pragma unroll
    for (int nt = 0; nt < 12; nt++) {
        const int j = nt * 8 + qo;
        const float g0 = gm_s[j], g1 = gm_s[j + 1];
        const float t0 = bt_s[j], t1 = bt_s[j + 1];
        *(float2*)(Ms + r0 * MSTR + j) = make_float2(
            (c[nt][0] - mean0) * rstd0 * g0 + t0,
            (c[nt][1] - mean0) * rstd0 * g1 + t1);
        *(float2*)(Ms + r1 * MSTR + j) = make_float2(
            (c[nt][2] - mean1) * rstd1 * g0 + t0,
            (c[nt][3] - mean1) * rstd1 * g1 + t1);
    }
    __syncthreads();

    for (int i = t; i < 128 * 24; i += 256) {
        const int row = i / 24;
        const int c4  = i - row * 24;
        const int ge  = blockIdx.x * 128 + row;
        if (ge >= NT) continue;
        float4 o = *(const float4*)(Ms + row * MSTR + c4 * 4);
        ((float4*)(upd_out + (size_t)ge * FIL))[c4] = o;
    }
}

// ---------------- launch ----------------
extern "C" void kernel_launch(void* const* d_in, const int* in_sizes, int n_in,
                              void* d_out, int out_size) {
    const float* nodes = (const float*)d_in[0];
    const float* ef    = (const float*)d_in[1];
    const int*   edges = (const int*)  d_in[2];
    const float* Wm    = (const float*)d_in[3];
    const float* bm    = (const float*)d_in[4];
    const float* gm_m  = (const float*)d_in[5];
    const float* bt_m  = (const float*)d_in[6];
    const float* Wu    = (const float*)d_in[7];
    const float* bu    = (const float*)d_in[8];
    const float* gm_u  = (const float*)d_in[9];
    const float* bt_u  = (const float*)d_in[10];

    float* out = (float*)d_out;
    float* upd = out;                               // (B, N, FILTERS)
    float* msg = out + (size_t)Bq * Nn * FIL;       // (B, E, FILTERS)

    cudaFuncSetAttribute(edge_kernel_mma, cudaFuncAttributeMaxDynamicSharedMemorySize,
                         E_SMEM_BYTES);
    cudaFuncSetAttribute(node_kernel_mma, cudaFuncAttributeMaxDynamicSharedMemorySize,
                         N_SMEM_BYTES);

    pack_kernel<<<232, 256>>>(Wm, Wu);
    pre_kernel<<<(NT + 63) / 64, 256>>>(nodes);
    edge_kernel_mma<<<(Bq * Ee) / 128, 256, E_SMEM_BYTES>>>(
        ef, edges, bm, gm_m, bt_m, msg);
    node_kernel_mma<<<(NT + 127) / 128, 256, N_SMEM_BYTES>>>(
        nodes, bu, gm_u, bt_u, upd);
}

// round 15
// speedup vs baseline: 1.0897x; 1.0897x over previous
#include <cuda_runtime.h>
#include <cstdint>

#define Bq   8
#define Nn   5000
#define Ee   40000
#define Ff   64
#define FEe  16
#define FIL  96
#define DM   144
#define DU   160
#define LN_EPS 1e-3f
#define MSTR 104   // Ms row stride (words) — conflict-free
#define NT   (Bq * Nn)

__device__ __align__(16) float g_agg[(size_t)Bq * Nn * FIL];
__device__ __align__(16) float g_pre[(size_t)Bq * Nn * 192];   // [node][0:96]=src-term, [96:192]=dst-term

// packed bf16 hi/lo weight fragments (built once by pack_kernel)
__device__ __align__(16) uint4 g_Wpre[16 * 192];   // pre B: combined [Wm(0:64)|Wm(64:128)]
__device__ __align__(16) uint4 g_Wef[4 * 96];      // edge B: Wm[128:144]
__device__ __align__(16) uint4 g_Wun[40 * 96];     // node B: Wu

// ---------------- helpers ----------------
__device__ __forceinline__ void red4(float* addr, float4 v) {
    asm volatile("red.global.add.v4.f32 [%0], {%1,%2,%3,%4};"
                 :: "l"(addr), "f"(v.x), "f"(v.y), "f"(v.z), "f"(v.w) : "memory");
}
__device__ __forceinline__ uint32_t split_pair(float x, float y, uint32_t& lo2) {
    uint32_t h;
    asm("cvt.rn.bf16x2.f32 %0, %1, %2;" : "=r"(h) : "f"(y), "f"(x));
    float hx = __uint_as_float(h << 16);
    float hy = __uint_as_float(h & 0xffff0000u);
    float rx = x - hx, ry = y - hy;
    asm("cvt.rn.bf16x2.f32 %0, %1, %2;" : "=r"(lo2) : "f"(ry), "f"(rx));
    return h;
}
__device__ __forceinline__ void mma_bf16(float* c, const uint32_t* a,
                                         uint32_t b0, uint32_t b1) {
    asm volatile(
        "mma.sync.aligned.m16n8k16.row.col.f32.bf16.bf16.f32 "
        "{%0,%1,%2,%3}, {%4,%5,%6,%7}, {%8,%9}, {%0,%1,%2,%3};"
        : "+f"(c[0]), "+f"(c[1]), "+f"(c[2]), "+f"(c[3])
        : "r"(a[0]), "r"(a[1]), "r"(a[2]), "r"(a[3]), "r"(b0), "r"(b1));
}
// read-only (nc-path) load + split of one 16-wide k-slab
__device__ __forceinline__ void load_split_nc(const float* p, int off,
                                              uint32_t& h0, uint32_t& h2,
                                              uint32_t& l0, uint32_t& l2) {
    float2 x0 = __ldg((const float2*)(p + off));
    float2 x2 = __ldg((const float2*)(p + off + 8));
    h0 = split_pair(x0.x, x0.y, l0);
    h2 = split_pair(x2.x, x2.y, l2);
}

// ================= pack kernel (unchanged) =================
__global__ void __launch_bounds__(256) pack_kernel(
    const float* __restrict__ Wm, const float* __restrict__ Wu)
{
    const int t = threadIdx.x;
    const size_t gtid = (size_t)blockIdx.x * 256 + t;
    const size_t gstr = (size_t)gridDim.x * 256;

    {
        float4* p = (float4*)g_agg;
        for (size_t i = gtid; i < (size_t)NT * FIL / 4; i += gstr)
            p[i] = make_float4(0.f, 0.f, 0.f, 0.f);
    }
    for (size_t i = gtid; i < 16 * 192; i += gstr) {
        int slot = (int)i / 192, n = (int)i - slot * 192;
        int kt = slot >> 2, qs = slot & 3;
        int ka = (kt * 8 + qs) * 2;
        int kb = ka + 8;
        const int col = (n < 96) ? n : (n - 96);
        const int ro  = (n < 96) ? 0 : 64;
        uint32_t la, lb;
        uint32_t ha = split_pair(Wm[(ro + ka) * FIL + col], Wm[(ro + ka + 1) * FIL + col], la);
        uint32_t hb = split_pair(Wm[(ro + kb) * FIL + col], Wm[(ro + kb + 1) * FIL + col], lb);
        g_Wpre[slot * 192 + (n ^ (2 * qs))] = make_uint4(ha, hb, la, lb);
    }
    for (size_t i = gtid; i < 4 * 96; i += gstr) {
        int qs = (int)i / 96, n = (int)i - qs * 96;
        uint32_t la, lb;
        uint32_t ha = split_pair(Wm[(128 + 2 * qs) * FIL + n], Wm[(129 + 2 * qs) * FIL + n], la);
        uint32_t hb = split_pair(Wm[(136 + 2 * qs) * FIL + n], Wm[(137 + 2 * qs) * FIL + n], lb);
        g_Wef[qs * 96 + (n ^ (2 * qs))] = make_uint4(ha, hb, la, lb);
    }
    for (size_t i = gtid; i < 40 * 96; i += gstr) {
        int slot = (int)i / 96, n = (int)i - slot * 96;
        int kt = slot >> 2, q = slot & 3;
        int k2a = kt * 8 + q, k2b = k2a + 4;
        uint32_t la, lb;
        uint32_t ha = split_pair(Wu[(2 * k2a) * FIL + n], Wu[(2 * k2a + 1) * FIL + n], la);
        uint32_t hb = split_pair(Wu[(2 * k2b) * FIL + n], Wu[(2 * k2b + 1) * FIL + n], lb);
        g_Wun[slot * 96 + (n ^ (2 * q))] = make_uint4(ha, hb, la, lb);
    }
}

// ================= pre kernel (R13 form + nc loads) =================
__global__ void __launch_bounds__(256, 2) pre_kernel(
    const float* __restrict__ nodes)
{
    const int t = threadIdx.x;
    const int lane = t & 31;
    const int w    = t >> 5;
    const int g    = lane >> 2;
    const int q    = lane & 3;
    const int r0 = w * 16 + g;
    const int gn0 = blockIdx.x * 128 + r0;
    const int gn1 = gn0 + 8;
    const int g0c = gn0 < NT ? gn0 : NT - 1;
    const int g1c = gn1 < NT ? gn1 : NT - 1;
    const float* n0 = nodes + (size_t)g0c * Ff;
    const float* n1 = nodes + (size_t)g1c * Ff;

    float c[24][4];
    #pragma unroll
    for (int nt = 0; nt < 24; nt++) { c[nt][0]=0.f; c[nt][1]=0.f; c[nt][2]=0.f; c[nt][3]=0.f; }

    const int gsw = g ^ (2 * q);
    const int qo  = 2 * q;

    #pragma unroll
    for (int kt = 0; kt < 4; kt++) {
        uint32_t ah[4], al[4];
        load_split_nc(n0, kt * 16 + qo, ah[0], ah[2], al[0], al[2]);
        load_split_nc(n1, kt * 16 + qo, ah[1], ah[3], al[1], al[3]);
        const uint4* Bp = g_Wpre + (kt * 4 + q) * 192 + gsw;
        #pragma unroll
        for (int nt = 0; nt < 24; nt++) {
            uint4 Bv = __ldg(Bp + nt * 8);
            mma_bf16(c[nt], ah, Bv.x, Bv.y);
            mma_bf16(c[nt], al, Bv.x, Bv.y);
            mma_bf16(c[nt], ah, Bv.z, Bv.w);
        }
    }

    if (gn0 < NT) {
        float* o = g_pre + (size_t)gn0 * 192 + qo;
        #pragma unroll
        for (int nt = 0; nt < 24; nt++)
            *(float2*)(o + nt * 8) = make_float2(c[nt][0], c[nt][1]);
    }
    if (gn1 < NT) {
        float* o = g_pre + (size_t)gn1 * 192 + qo;
        #pragma unroll
        for (int nt = 0; nt < 24; nt++)
            *(float2*)(o + nt * 8) = make_float2(c[nt][2], c[nt][3]);
    }
}

// ================= edge kernel (R13 form + nc loads + streaming stores) =================
#define XS_MS    0             // 128 x 104 = 13312 words
#define XS_BM    13312
#define XS_GM    13408
#define XS_BT    13504
#define XS_SEB   13600         // 128 int2 = 256 words
#define XS_TOTAL 13856
#define E_SMEM_BYTES (XS_TOTAL * 4)

__global__ void __launch_bounds__(256, 3) edge_kernel_mma(
    const float* __restrict__ ef,    const int*   __restrict__ edges,
    const float* __restrict__ bm,    const float* __restrict__ gm,
    const float* __restrict__ bt,    float* __restrict__ msg_out)
{
    extern __shared__ float sm[];
    float* Ms   = sm + XS_MS;         // stride MSTR
    float* bm_s = sm + XS_BM;
    float* gm_s = sm + XS_GM;
    float* bt_s = sm + XS_BT;
    int2*  seb  = (int2*)(sm + XS_SEB);

    const int t = threadIdx.x;

    if (t < FIL) { bm_s[t] = bm[t]; gm_s[t] = gm[t]; bt_s[t] = bt[t]; }
    if (t < 128) seb[t] = __ldg(((const int2*)edges) + blockIdx.x * 128 + t);
    __syncthreads();

    const int lane = t & 31;
    const int w    = t >> 5;
    const int g    = lane >> 2;
    const int q    = lane & 3;
    const int r0 = w * 16 + g, r1 = r0 + 8;
    const int ge0 = blockIdx.x * 128 + r0;
    const int ge1 = ge0 + 8;
    const int b0 = ge0 / Ee, b1 = ge1 / Ee;
    const int2 e0 = seb[r0], e1 = seb[r1];
    const int gsw = g ^ (2 * q);
    const int qo  = 2 * q;

    // ---- init accumulators with gathered g_pre terms + bias (nc loads lead) ----
    const float* pA = g_pre + (size_t)(b0 * Nn + e0.x) * 192;
    const float* pB = g_pre + (size_t)(b0 * Nn + e0.y) * 192 + 96;
    const float* pC = g_pre + (size_t)(b1 * Nn + e1.x) * 192;
    const float* pD = g_pre + (size_t)(b1 * Nn + e1.y) * 192 + 96;

    float c[12][4];
    #pragma unroll
    for (int nt = 0; nt < 12; nt++) {
        const int j = nt * 8 + qo;
        float2 xa = __ldg((const float2*)(pA + j));
        float2 xb = __ldg((const float2*)(pB + j));
        float2 xc = __ldg((const float2*)(pC + j));
        float2 xd = __ldg((const float2*)(pD + j));
        const float bv0 = bm_s[j], bv1 = bm_s[j + 1];
        c[nt][0] = xa.x + xb.x + bv0;
        c[nt][1] = xa.y + xb.y + bv1;
        c[nt][2] = xc.x + xd.x + bv0;
        c[nt][3] = xc.y + xd.y + bv1;
    }

    // ---- ef GEMM accumulates on top: single k-step, 3 terms ----
    {
        uint32_t ah[4], al[4];
        load_split_nc(ef + (size_t)ge0 * FEe, qo, ah[0], ah[2], al[0], al[2]);
        load_split_nc(ef + (size_t)ge1 * FEe, qo, ah[1], ah[3], al[1], al[3]);
        const uint4* Bp = g_Wef + q * 96 + gsw;
        #pragma unroll
        for (int nt = 0; nt < 12; nt++) {
            uint4 Bv = __ldg(Bp + nt * 8);
            mma_bf16(c[nt], ah, Bv.x, Bv.y);
            mma_bf16(c[nt], al, Bv.x, Bv.y);
            mma_bf16(c[nt], ah, Bv.z, Bv.w);
        }
    }

    // ---- relu + LN stats ----
    float sum0 = 0.f, sq0 = 0.f, sum1 = 0.f, sq1 = 0.f;
    #pragma unroll
    for (int nt = 0; nt < 12; nt++) {
        float v0 = fmaxf(c[nt][0], 0.f);
        float v1 = fmaxf(c[nt][1], 0.f);
        float v2 = fmaxf(c[nt][2], 0.f);
        float v3 = fmaxf(c[nt][3], 0.f);
        c[nt][0] = v0; c[nt][1] = v1; c[nt][2] = v2; c[nt][3] = v3;
        sum0 += v0 + v1;  sq0 += v0 * v0 + v1 * v1;
        sum1 += v2 + v3;  sq1 += v2 * v2 + v3 * v3;
    }
    #pragma unroll
    for (int m = 1; m < 4; m <<= 1) {
        sum0 += __shfl_xor_sync(0xffffffffu, sum0, m);
        sq0  += __shfl_xor_sync(0xffffffffu, sq0,  m);
        sum1 += __shfl_xor_sync(0xffffffffu, sum1, m);
        sq1  += __shfl_xor_sync(0xffffffffu, sq1,  m);
    }
    const float mean0 = sum0 * (1.f / FIL);
    const float rstd0 = rsqrtf(sq0 * (1.f / FIL) - mean0 * mean0 + LN_EPS);
    const float mean1 = sum1 * (1.f / FIL);
    const float rstd1 = rsqrtf(sq1 * (1.f / FIL) - mean1 * mean1 + LN_EPS);

    // ---- apply LN, stage ----
    #pragma unroll
    for (int nt = 0; nt < 12; nt++) {
        const int j = nt * 8 + qo;
        const float g0 = gm_s[j], g1 = gm_s[j + 1];
        const float t0 = bt_s[j], t1 = bt_s[j + 1];
        *(float2*)(Ms + r0 * MSTR + j) = make_float2(
            (c[nt][0] - mean0) * rstd0 * g0 + t0,
            (c[nt][1] - mean0) * rstd0 * g1 + t1);
        *(float2*)(Ms + r1 * MSTR + j) = make_float2(
            (c[nt][2] - mean1) * rstd1 * g0 + t0,
            (c[nt][3] - mean1) * rstd1 * g1 + t1);
    }
    __syncthreads();

    // ---- coalesced streaming store + vector atomics ----
    for (int i = t; i < 128 * 24; i += 256) {
        const int row = i / 24;
        const int c4  = i - row * 24;
        const int j   = c4 * 4;
        float4 o = *(const float4*)(Ms + row * MSTR + j);
        const int ge = blockIdx.x * 128 + row;
        const int b  = ge / Ee;
        __stcs((float4*)(msg_out + (size_t)ge * FIL) + c4, o);
        red4(g_agg + ((size_t)b * Nn + seb[row].y) * FIL + j, o);
    }
}

// ================= node kernel (R13 form + nc loads + streaming stores) =================
#define NS_MS    0             // 128 x 104 = 13312 words
#define NS_BM    13312
#define NS_GM    13408
#define NS_BT    13504
#define NS_TOTAL 13600
#define N_SMEM_BYTES (NS_TOTAL * 4)

__global__ void __launch_bounds__(256, 2) node_kernel_mma(
    const float* __restrict__ nodes, const float* __restrict__ bu,
    const float* __restrict__ gm,    const float* __restrict__ bt,
    float* __restrict__ upd_out)
{
    extern __shared__ float sm[];
    float* Ms   = sm + NS_MS;
    float* bm_s = sm + NS_BM;
    float* gm_s = sm + NS_GM;
    float* bt_s = sm + NS_BT;

    const int t = threadIdx.x;

    if (t < FIL) { bm_s[t] = bu[t]; gm_s[t] = gm[t]; bt_s[t] = bt[t]; }
    __syncthreads();

    const int lane = t & 31;
    const int w    = t >> 5;
    const int g    = lane >> 2;
    const int q    = lane & 3;
    const int r0 = w * 16 + g, r1 = r0 + 8;

    const int gn0 = blockIdx.x * 128 + r0;
    const int gn1 = gn0 + 8;
    const int g0c = gn0 < NT ? gn0 : NT - 1;
    const int g1c = gn1 < NT ? gn1 : NT - 1;
    const float* n0 = nodes + (size_t)g0c * Ff;
    const float* n1 = nodes + (size_t)g1c * Ff;
    const float* a0 = g_agg + (size_t)g0c * FIL;
    const float* a1 = g_agg + (size_t)g1c * FIL;

    float c[12][4];
    #pragma unroll
    for (int nt = 0; nt < 12; nt++) { c[nt][0]=0.f; c[nt][1]=0.f; c[nt][2]=0.f; c[nt][3]=0.f; }

    const int gsw = g ^ (2 * q);
    const int qo  = 2 * q;

    #pragma unroll
    for (int kt = 0; kt < 10; kt++) {
        const float *p0, *p1;
        int off;
        if (kt < 4) { p0 = n0; p1 = n1; off = kt * 16; }
        else        { p0 = a0; p1 = a1; off = (kt - 4) * 16; }
        off += qo;

        uint32_t ah[4], al[4];
        load_split_nc(p0, off, ah[0], ah[2], al[0], al[2]);
        load_split_nc(p1, off, ah[1], ah[3], al[1], al[3]);

        const uint4* Bp = g_Wun + (kt * 4 + q) * 96 + gsw;
        #pragma unroll
        for (int nt = 0; nt < 12; nt++) {
            uint4 Bv = __ldg(Bp + nt * 8);
            mma_bf16(c[nt], ah, Bv.x, Bv.y);
            mma_bf16(c[nt], al, Bv.x, Bv.y);
            mma_bf16(c[nt], ah, Bv.z, Bv.w);
        }
    }

    float sum0 = 0.f, sq0 = 0.f, sum1 = 0.f, sq1 = 0.f;
    #pragma unroll
    for (int nt = 0; nt < 12; nt++) {
        const int j = nt * 8 + qo;
        const float bv0 = bm_s[j], bv1 = bm_s[j + 1];
        float v0 = fmaxf(c[nt][0] + bv0, 0.f);
        float v1 = fmaxf(c[nt][1] + bv1, 0.f);
        float v2 = fmaxf(c[nt][2] + bv0, 0.f);
        float v3 = fmaxf(c[nt][3] + bv1, 0.f);
        c[nt][0] = v0; c[nt][1] = v1; c[nt][2] = v2; c[nt][3] = v3;
        sum0 += v0 + v1;  sq0 += v0 * v0 + v1 * v1;
        sum1 += v2 + v3;  sq1 += v2 * v2 + v3 * v3;
    }
    #pragma unroll
    for (int m = 1; m < 4; m <<= 1) {
        sum0 += __shfl_xor_sync(0xffffffffu, sum0, m);
        sq0  += __shfl_xor_sync(0xffffffffu, sq0,  m);
        sum1 += __shfl_xor_sync(0xffffffffu, sum1, m);
        sq1  += __shfl_xor_sync(0xffffffffu, sq1,  m);
    }
    const float mean0 = sum0 * (1.f / FIL);
    const float rstd0 = rsqrtf(sq0 * (1.f / FIL) - mean0 * mean0 + LN_EPS);
    const float mean1 = sum1 * (1.f / FIL);
    const float rstd1 = rsqrtf(sq1 * (1.f / FIL) - mean1 * mean1 + LN_EPS);

    #pragma unroll
    for (int nt = 0; nt < 12; nt++) {
        const int j = nt * 8 + qo;
        const float g0 = gm_s[j], g1 = gm_s[j + 1];
        const float t0 = bt_s[j], t1 = bt_s[j + 1];
        *(float2*)(Ms + r0 * MSTR + j) = make_float2(
            (c[nt][0] - mean0) * rstd0 * g0 + t0,
            (c[nt][1] - mean0) * rstd0 * g1 + t1);
        *(float2*)(Ms + r1 * MSTR + j) = make_float2(
            (c[nt][2] - mean1) * rstd1 * g0 + t0,
            (c[nt][3] - mean1) * rstd1 * g1 + t1);
    }
    __syncthreads();

    for (int i = t; i < 128 * 24; i += 256) {
        const int row = i / 24;
        const int c4  = i - row * 24;
        const int ge  = blockIdx.x * 128 + row;
        if (ge >= NT) continue;
        float4 o = *(const float4*)(Ms + row * MSTR + c4 * 4);
        __stcs((float4*)(upd_out + (size_t)ge * FIL) + c4, o);
    }
}

// ---------------- launch ----------------
extern "C" void kernel_launch(void* const* d_in, const int* in_sizes, int n_in,
                              void* d_out, int out_size) {
    const float* nodes = (const float*)d_in[0];
    const float* ef    = (const float*)d_in[1];
    const int*   edges = (const int*)  d_in[2];
    const float* Wm    = (const float*)d_in[3];
    const float* bm    = (const float*)d_in[4];
    const float* gm_m  = (const float*)d_in[5];
    const float* bt_m  = (const float*)d_in[6];
    const float* Wu    = (const float*)d_in[7];
    const float* bu    = (const float*)d_in[8];
    const float* gm_u  = (const float*)d_in[9];
    const float* bt_u  = (const float*)d_in[10];

    float* out = (float*)d_out;
    float* upd = out;                               // (B, N, FILTERS)
    float* msg = out + (size_t)Bq * Nn * FIL;       // (B, E, FILTERS)

    cudaFuncSetAttribute(edge_kernel_mma, cudaFuncAttributeMaxDynamicSharedMemorySize,
                         E_SMEM_BYTES);
    cudaFuncSetAttribute(node_kernel_mma, cudaFuncAttributeMaxDynamicSharedMemorySize,
                         N_SMEM_BYTES);

    pack_kernel<<<232, 256>>>(Wm, Wu);
    pre_kernel<<<(NT + 127) / 128, 256>>>(nodes);
    edge_kernel_mma<<<(Bq * Ee) / 128, 256, E_SMEM_BYTES>>>(
        ef, edges, bm, gm_m, bt_m, msg);
    node_kernel_mma<<<(NT + 127) / 128, 256, N_SMEM_BYTES>>>(
        nodes, bu, gm_u, bt_u, upd);
}

// round 16
// speedup vs baseline: 1.1117x; 1.0201x over previous
#include <cuda_runtime.h>
#include <cstdint>

#define Bq   8
#define Nn   5000
#define Ee   40000
#define Ff   64
#define FEe  16
#define FIL  96
#define DM   144
#define DU   160
#define LN_EPS 1e-3f
#define MSTR 104   // Ms row stride (words) — conflict-free
#define NT   (Bq * Nn)

__device__ __align__(16) float g_agg[(size_t)Bq * Nn * FIL];
__device__ __align__(16) float g_pre[(size_t)Bq * Nn * 192];   // [node][0:96]=src-term, [96:192]=dst-term

// packed bf16 hi/lo weight fragments (built once by pack_kernel)
__device__ __align__(16) uint4 g_Wpre[16 * 192];   // pre B: combined [Wm(0:64)|Wm(64:128)]
__device__ __align__(16) uint4 g_Wef[4 * 96];      // edge B: Wm[128:144]
__device__ __align__(16) uint4 g_Wun[40 * 96];     // node B: Wu

// ---------------- helpers ----------------
__device__ __forceinline__ void red4(float* addr, float4 v) {
    asm volatile("red.global.add.v4.f32 [%0], {%1,%2,%3,%4};"
                 :: "l"(addr), "f"(v.x), "f"(v.y), "f"(v.z), "f"(v.w) : "memory");
}
__device__ __forceinline__ uint32_t split_pair(float x, float y, uint32_t& lo2) {
    uint32_t h;
    asm("cvt.rn.bf16x2.f32 %0, %1, %2;" : "=r"(h) : "f"(y), "f"(x));
    float hx = __uint_as_float(h << 16);
    float hy = __uint_as_float(h & 0xffff0000u);
    float rx = x - hx, ry = y - hy;
    asm("cvt.rn.bf16x2.f32 %0, %1, %2;" : "=r"(lo2) : "f"(ry), "f"(rx));
    return h;
}
__device__ __forceinline__ void mma_bf16(float* c, const uint32_t* a,
                                         uint32_t b0, uint32_t b1) {
    asm volatile(
        "mma.sync.aligned.m16n8k16.row.col.f32.bf16.bf16.f32 "
        "{%0,%1,%2,%3}, {%4,%5,%6,%7}, {%8,%9}, {%0,%1,%2,%3};"
        : "+f"(c[0]), "+f"(c[1]), "+f"(c[2]), "+f"(c[3])
        : "r"(a[0]), "r"(a[1]), "r"(a[2]), "r"(a[3]), "r"(b0), "r"(b1));
}
// read-only (nc-path) load + split of one 16-wide k-slab
__device__ __forceinline__ void load_split_nc(const float* p, int off,
                                              uint32_t& h0, uint32_t& h2,
                                              uint32_t& l0, uint32_t& l2) {
    float2 x0 = __ldg((const float2*)(p + off));
    float2 x2 = __ldg((const float2*)(p + off + 8));
    h0 = split_pair(x0.x, x0.y, l0);
    h2 = split_pair(x2.x, x2.y, l2);
}

// ================= pack kernel (unchanged) =================
__global__ void __launch_bounds__(256) pack_kernel(
    const float* __restrict__ Wm, const float* __restrict__ Wu)
{
    const int t = threadIdx.x;
    const size_t gtid = (size_t)blockIdx.x * 256 + t;
    const size_t gstr = (size_t)gridDim.x * 256;

    {
        float4* p = (float4*)g_agg;
        for (size_t i = gtid; i < (size_t)NT * FIL / 4; i += gstr)
            p[i] = make_float4(0.f, 0.f, 0.f, 0.f);
    }
    for (size_t i = gtid; i < 16 * 192; i += gstr) {
        int slot = (int)i / 192, n = (int)i - slot * 192;
        int kt = slot >> 2, qs = slot & 3;
        int ka = (kt * 8 + qs) * 2;
        int kb = ka + 8;
        const int col = (n < 96) ? n : (n - 96);
        const int ro  = (n < 96) ? 0 : 64;
        uint32_t la, lb;
        uint32_t ha = split_pair(Wm[(ro + ka) * FIL + col], Wm[(ro + ka + 1) * FIL + col], la);
        uint32_t hb = split_pair(Wm[(ro + kb) * FIL + col], Wm[(ro + kb + 1) * FIL + col], lb);
        g_Wpre[slot * 192 + (n ^ (2 * qs))] = make_uint4(ha, hb, la, lb);
    }
    for (size_t i = gtid; i < 4 * 96; i += gstr) {
        int qs = (int)i / 96, n = (int)i - qs * 96;
        uint32_t la, lb;
        uint32_t ha = split_pair(Wm[(128 + 2 * qs) * FIL + n], Wm[(129 + 2 * qs) * FIL + n], la);
        uint32_t hb = split_pair(Wm[(136 + 2 * qs) * FIL + n], Wm[(137 + 2 * qs) * FIL + n], lb);
        g_Wef[qs * 96 + (n ^ (2 * qs))] = make_uint4(ha, hb, la, lb);
    }
    for (size_t i = gtid; i < 40 * 96; i += gstr) {
        int slot = (int)i / 96, n = (int)i - slot * 96;
        int kt = slot >> 2, q = slot & 3;
        int k2a = kt * 8 + q, k2b = k2a + 4;
        uint32_t la, lb;
        uint32_t ha = split_pair(Wu[(2 * k2a) * FIL + n], Wu[(2 * k2a + 1) * FIL + n], la);
        uint32_t hb = split_pair(Wu[(2 * k2b) * FIL + n], Wu[(2 * k2b + 1) * FIL + n], lb);
        g_Wun[slot * 96 + (n ^ (2 * q))] = make_uint4(ha, hb, la, lb);
    }
}

// ================= pre kernel: 64 rows/block, 128 threads, 4 CTAs/SM =================
__global__ void __launch_bounds__(128, 4) pre_kernel(
    const float* __restrict__ nodes)
{
    const int t = threadIdx.x;
    const int lane = t & 31;
    const int w    = t >> 5;          // 0..3
    const int g    = lane >> 2;
    const int q    = lane & 3;
    const int r0 = w * 16 + g;
    const int gn0 = blockIdx.x * 64 + r0;
    const int gn1 = gn0 + 8;
    const int g0c = gn0 < NT ? gn0 : NT - 1;
    const int g1c = gn1 < NT ? gn1 : NT - 1;
    const float* n0 = nodes + (size_t)g0c * Ff;
    const float* n1 = nodes + (size_t)g1c * Ff;

    float c[24][4];
    #pragma unroll
    for (int nt = 0; nt < 24; nt++) { c[nt][0]=0.f; c[nt][1]=0.f; c[nt][2]=0.f; c[nt][3]=0.f; }

    const int gsw = g ^ (2 * q);
    const int qo  = 2 * q;

    #pragma unroll
    for (int kt = 0; kt < 4; kt++) {
        uint32_t ah[4], al[4];
        load_split_nc(n0, kt * 16 + qo, ah[0], ah[2], al[0], al[2]);
        load_split_nc(n1, kt * 16 + qo, ah[1], ah[3], al[1], al[3]);
        const uint4* Bp = g_Wpre + (kt * 4 + q) * 192 + gsw;
        #pragma unroll
        for (int nt = 0; nt < 24; nt++) {
            uint4 Bv = __ldg(Bp + nt * 8);
            mma_bf16(c[nt], ah, Bv.x, Bv.y);
            mma_bf16(c[nt], al, Bv.x, Bv.y);
            mma_bf16(c[nt], ah, Bv.z, Bv.w);
        }
    }

    if (gn0 < NT) {
        float* o = g_pre + (size_t)gn0 * 192 + qo;
        #pragma unroll
        for (int nt = 0; nt < 24; nt++)
            *(float2*)(o + nt * 8) = make_float2(c[nt][0], c[nt][1]);
    }
    if (gn1 < NT) {
        float* o = g_pre + (size_t)gn1 * 192 + qo;
        #pragma unroll
        for (int nt = 0; nt < 24; nt++)
            *(float2*)(o + nt * 8) = make_float2(c[nt][2], c[nt][3]);
    }
}

// ================= edge kernel (unchanged from R15) =================
#define XS_MS    0             // 128 x 104 = 13312 words
#define XS_BM    13312
#define XS_GM    13408
#define XS_BT    13504
#define XS_SEB   13600         // 128 int2 = 256 words
#define XS_TOTAL 13856
#define E_SMEM_BYTES (XS_TOTAL * 4)

__global__ void __launch_bounds__(256, 3) edge_kernel_mma(
    const float* __restrict__ ef,    const int*   __restrict__ edges,
    const float* __restrict__ bm,    const float* __restrict__ gm,
    const float* __restrict__ bt,    float* __restrict__ msg_out)
{
    extern __shared__ float sm[];
    float* Ms   = sm + XS_MS;
    float* bm_s = sm + XS_BM;
    float* gm_s = sm + XS_GM;
    float* bt_s = sm + XS_BT;
    int2*  seb  = (int2*)(sm + XS_SEB);

    const int t = threadIdx.x;

    if (t < FIL) { bm_s[t] = bm[t]; gm_s[t] = gm[t]; bt_s[t] = bt[t]; }
    if (t < 128) seb[t] = __ldg(((const int2*)edges) + blockIdx.x * 128 + t);
    __syncthreads();

    const int lane = t & 31;
    const int w    = t >> 5;
    const int g    = lane >> 2;
    const int q    = lane & 3;
    const int r0 = w * 16 + g, r1 = r0 + 8;
    const int ge0 = blockIdx.x * 128 + r0;
    const int ge1 = ge0 + 8;
    const int b0 = ge0 / Ee, b1 = ge1 / Ee;
    const int2 e0 = seb[r0], e1 = seb[r1];
    const int gsw = g ^ (2 * q);
    const int qo  = 2 * q;

    const float* pA = g_pre + (size_t)(b0 * Nn + e0.x) * 192;
    const float* pB = g_pre + (size_t)(b0 * Nn + e0.y) * 192 + 96;
    const float* pC = g_pre + (size_t)(b1 * Nn + e1.x) * 192;
    const float* pD = g_pre + (size_t)(b1 * Nn + e1.y) * 192 + 96;

    float c[12][4];
    #pragma unroll
    for (int nt = 0; nt < 12; nt++) {
        const int j = nt * 8 + qo;
        float2 xa = __ldg((const float2*)(pA + j));
        float2 xb = __ldg((const float2*)(pB + j));
        float2 xc = __ldg((const float2*)(pC + j));
        float2 xd = __ldg((const float2*)(pD + j));
        const float bv0 = bm_s[j], bv1 = bm_s[j + 1];
        c[nt][0] = xa.x + xb.x + bv0;
        c[nt][1] = xa.y + xb.y + bv1;
        c[nt][2] = xc.x + xd.x + bv0;
        c[nt][3] = xc.y + xd.y + bv1;
    }

    {
        uint32_t ah[4], al[4];
        load_split_nc(ef + (size_t)ge0 * FEe, qo, ah[0], ah[2], al[0], al[2]);
        load_split_nc(ef + (size_t)ge1 * FEe, qo, ah[1], ah[3], al[1], al[3]);
        const uint4* Bp = g_Wef + q * 96 + gsw;
        #pragma unroll
        for (int nt = 0; nt < 12; nt++) {
            uint4 Bv = __ldg(Bp + nt * 8);
            mma_bf16(c[nt], ah, Bv.x, Bv.y);
            mma_bf16(c[nt], al, Bv.x, Bv.y);
            mma_bf16(c[nt], ah, Bv.z, Bv.w);
        }
    }

    float sum0 = 0.f, sq0 = 0.f, sum1 = 0.f, sq1 = 0.f;
    #pragma unroll
    for (int nt = 0; nt < 12; nt++) {
        float v0 = fmaxf(c[nt][0], 0.f);
        float v1 = fmaxf(c[nt][1], 0.f);
        float v2 = fmaxf(c[nt][2], 0.f);
        float v3 = fmaxf(c[nt][3], 0.f);
        c[nt][0] = v0; c[nt][1] = v1; c[nt][2] = v2; c[nt][3] = v3;
        sum0 += v0 + v1;  sq0 += v0 * v0 + v1 * v1;
        sum1 += v2 + v3;  sq1 += v2 * v2 + v3 * v3;
    }
    #pragma unroll
    for (int m = 1; m < 4; m <<= 1) {
        sum0 += __shfl_xor_sync(0xffffffffu, sum0, m);
        sq0  += __shfl_xor_sync(0xffffffffu, sq0,  m);
        sum1 += __shfl_xor_sync(0xffffffffu, sum1, m);
        sq1  += __shfl_xor_sync(0xffffffffu, sq1,  m);
    }
    const float mean0 = sum0 * (1.f / FIL);
    const float rstd0 = rsqrtf(sq0 * (1.f / FIL) - mean0 * mean0 + LN_EPS);
    const float mean1 = sum1 * (1.f / FIL);
    const float rstd1 = rsqrtf(sq1 * (1.f / FIL) - mean1 * mean1 + LN_EPS);

    #pragma unroll
    for (int nt = 0; nt < 12; nt++) {
        const int j = nt * 8 + qo;
        const float g0 = gm_s[j], g1 = gm_s[j + 1];
        const float t0 = bt_s[j], t1 = bt_s[j + 1];
        *(float2*)(Ms + r0 * MSTR + j) = make_float2(
            (c[nt][0] - mean0) * rstd0 * g0 + t0,
            (c[nt][1] - mean0) * rstd0 * g1 + t1);
        *(float2*)(Ms + r1 * MSTR + j) = make_float2(
            (c[nt][2] - mean1) * rstd1 * g0 + t0,
            (c[nt][3] - mean1) * rstd1 * g1 + t1);
    }
    __syncthreads();

    for (int i = t; i < 128 * 24; i += 256) {
        const int row = i / 24;
        const int c4  = i - row * 24;
        const int j   = c4 * 4;
        float4 o = *(const float4*)(Ms + row * MSTR + j);
        const int ge = blockIdx.x * 128 + row;
        const int b  = ge / Ee;
        __stcs((float4*)(msg_out + (size_t)ge * FIL) + c4, o);
        red4(g_agg + ((size_t)b * Nn + seb[row].y) * FIL + j, o);
    }
}

// ================= node kernel: 64 rows/block, 128 threads, 4 CTAs/SM =================
#define NS_MS    0             // 64 x 104 = 6656 words
#define NS_BM    6656
#define NS_GM    6752
#define NS_BT    6848
#define NS_TOTAL 6944
#define N_SMEM_BYTES (NS_TOTAL * 4)

__global__ void __launch_bounds__(128, 4) node_kernel_mma(
    const float* __restrict__ nodes, const float* __restrict__ bu,
    const float* __restrict__ gm,    const float* __restrict__ bt,
    float* __restrict__ upd_out)
{
    extern __shared__ float sm[];
    float* Ms   = sm + NS_MS;
    float* bm_s = sm + NS_BM;
    float* gm_s = sm + NS_GM;
    float* bt_s = sm + NS_BT;

    const int t = threadIdx.x;

    if (t < FIL) { bm_s[t] = bu[t]; gm_s[t] = gm[t]; bt_s[t] = bt[t]; }
    __syncthreads();

    const int lane = t & 31;
    const int w    = t >> 5;          // 0..3
    const int g    = lane >> 2;
    const int q    = lane & 3;
    const int r0 = w * 16 + g, r1 = r0 + 8;

    const int gn0 = blockIdx.x * 64 + r0;
    const int gn1 = gn0 + 8;
    const int g0c = gn0 < NT ? gn0 : NT - 1;
    const int g1c = gn1 < NT ? gn1 : NT - 1;
    const float* n0 = nodes + (size_t)g0c * Ff;
    const float* n1 = nodes + (size_t)g1c * Ff;
    const float* a0 = g_agg + (size_t)g0c * FIL;
    const float* a1 = g_agg + (size_t)g1c * FIL;

    float c[12][4];
    #pragma unroll
    for (int nt = 0; nt < 12; nt++) { c[nt][0]=0.f; c[nt][1]=0.f; c[nt][2]=0.f; c[nt][3]=0.f; }

    const int gsw = g ^ (2 * q);
    const int qo  = 2 * q;

    #pragma unroll
    for (int kt = 0; kt < 10; kt++) {
        const float *p0, *p1;
        int off;
        if (kt < 4) { p0 = n0; p1 = n1; off = kt * 16; }
        else        { p0 = a0; p1 = a1; off = (kt - 4) * 16; }
        off += qo;

        uint32_t ah[4], al[4];
        load_split_nc(p0, off, ah[0], ah[2], al[0], al[2]);
        load_split_nc(p1, off, ah[1], ah[3], al[1], al[3]);

        const uint4* Bp = g_Wun + (kt * 4 + q) * 96 + gsw;
        #pragma unroll
        for (int nt = 0; nt < 12; nt++) {
            uint4 Bv = __ldg(Bp + nt * 8);
            mma_bf16(c[nt], ah, Bv.x, Bv.y);
            mma_bf16(c[nt], al, Bv.x, Bv.y);
            mma_bf16(c[nt], ah, Bv.z, Bv.w);
        }
    }

    float sum0 = 0.f, sq0 = 0.f, sum1 = 0.f, sq1 = 0.f;
    #pragma unroll
    for (int nt = 0; nt < 12; nt++) {
        const int j = nt * 8 + qo;
        const float bv0 = bm_s[j], bv1 = bm_s[j + 1];
        float v0 = fmaxf(c[nt][0] + bv0, 0.f);
        float v1 = fmaxf(c[nt][1] + bv1, 0.f);
        float v2 = fmaxf(c[nt][2] + bv0, 0.f);
        float v3 = fmaxf(c[nt][3] + bv1, 0.f);
        c[nt][0] = v0; c[nt][1] = v1; c[nt][2] = v2; c[nt][3] = v3;
        sum0 += v0 + v1;  sq0 += v0 * v0 + v1 * v1;
        sum1 += v2 + v3;  sq1 += v2 * v2 + v3 * v3;
    }
    #pragma unroll
    for (int m = 1; m < 4; m <<= 1) {
        sum0 += __shfl_xor_sync(0xffffffffu, sum0, m);
        sq0  += __shfl_xor_sync(0xffffffffu, sq0,  m);
        sum1 += __shfl_xor_sync(0xffffffffu, sum1, m);
        sq1  += __shfl_xor_sync(0xffffffffu, sq1,  m);
    }
    const float mean0 = sum0 * (1.f / FIL);
    const float rstd0 = rsqrtf(sq0 * (1.f / FIL) - mean0 * mean0 + LN_EPS);
    const float mean1 = sum1 * (1.f / FIL);
    const float rstd1 = rsqrtf(sq1 * (1.f / FIL) - mean1 * mean1 + LN_EPS);

    #pragma unroll
    for (int nt = 0; nt < 12; nt++) {
        const int j = nt * 8 + qo;
        const float g0 = gm_s[j], g1 = gm_s[j + 1];
        const float t0 = bt_s[j], t1 = bt_s[j + 1];
        *(float2*)(Ms + r0 * MSTR + j) = make_float2(
            (c[nt][0] - mean0) * rstd0 * g0 + t0,
            (c[nt][1] - mean0) * rstd0 * g1 + t1);
        *(float2*)(Ms + r1 * MSTR + j) = make_float2(
            (c[nt][2] - mean1) * rstd1 * g0 + t0,
            (c[nt][3] - mean1) * rstd1 * g1 + t1);
    }
    __syncthreads();

    for (int i = t; i < 64 * 24; i += 128) {
        const int row = i / 24;
        const int c4  = i - row * 24;
        const int ge  = blockIdx.x * 64 + row;
        if (ge >= NT) continue;
        float4 o = *(const float4*)(Ms + row * MSTR + c4 * 4);
        __stcs((float4*)(upd_out + (size_t)ge * FIL) + c4, o);
    }
}

// ---------------- launch ----------------
extern "C" void kernel_launch(void* const* d_in, const int* in_sizes, int n_in,
                              void* d_out, int out_size) {
    const float* nodes = (const float*)d_in[0];
    const float* ef    = (const float*)d_in[1];
    const int*   edges = (const int*)  d_in[2];
    const float* Wm    = (const float*)d_in[3];
    const float* bm    = (const float*)d_in[4];
    const float* gm_m  = (const float*)d_in[5];
    const float* bt_m  = (const float*)d_in[6];
    const float* Wu    = (const float*)d_in[7];
    const float* bu    = (const float*)d_in[8];
    const float* gm_u  = (const float*)d_in[9];
    const float* bt_u  = (const float*)d_in[10];

    float* out = (float*)d_out;
    float* upd = out;                               // (B, N, FILTERS)
    float* msg = out + (size_t)Bq * Nn * FIL;       // (B, E, FILTERS)

    cudaFuncSetAttribute(edge_kernel_mma, cudaFuncAttributeMaxDynamicSharedMemorySize,
                         E_SMEM_BYTES);
    cudaFuncSetAttribute(node_kernel_mma, cudaFuncAttributeMaxDynamicSharedMemorySize,
                         N_SMEM_BYTES);

    pack_kernel<<<232, 256>>>(Wm, Wu);
    pre_kernel<<<(NT + 63) / 64, 128>>>(nodes);
    edge_kernel_mma<<<(Bq * Ee) / 128, 256, E_SMEM_BYTES>>>(
        ef, edges, bm, gm_m, bt_m, msg);
    node_kernel_mma<<<(NT + 63) / 64, 128, N_SMEM_BYTES>>>(
        nodes, bu, gm_u, bt_u, upd);
}